// round 8
// baseline (speedup 1.0000x reference)
#include <cuda_runtime.h>
#include <cstdint>

#define GN    8192
#define LMBD  0.1f
#define QCAP  64
#define QEFF  (QCAP - 4)
#define FULLM 0xffffffffu

__device__ float    g_sum;     // zero-init; reset by last block each launch
__device__ unsigned g_count;

// One block per row of A (8192 x 256). Warp w owns cols [w*1024,(w+1)*1024),
// scanned as 2 chunks of 4 float4/lane; chunk-1 A-loads in flight during
// drain of chunk 0. Compaction: 1 ballot/float4, first nz queued as scalar
// (a, j); extra components & overflow handled once per chunk (deferred ballot).
// Drain: 8-lane dot groups (lane holds 16 elems of Y[row]); each iteration
// processes 4 queue entries with all 16 W-loads batched before the single
// 3-stage shuffle reduce. b folded: pred = W[j].Y[i] + b.Y[i].
__global__ void __launch_bounds__(256, 5)
main_kernel(const float* __restrict__ A, const float* __restrict__ W,
            const float* __restrict__ b, float* __restrict__ out) {
    __shared__ float qa[8][QCAP];
    __shared__ int   qj[8][QCAP];
    __shared__ float sp[8];

    const int row  = blockIdx.x;
    const int w    = threadIdx.x >> 5;
    const int lane = threadIdx.x & 31;
    const int gl   = lane & 7;     // lane within 8-lane group
    const int grp  = lane >> 3;    // group 0..3
    const unsigned ltm = (1u << lane) - 1u;

    const float4* __restrict__ A4 =
        reinterpret_cast<const float4*>(A) + (size_t)row * (GN / 4);
    const float4* __restrict__ W4 = reinterpret_cast<const float4*>(W);
    const float4* __restrict__ B4 = reinterpret_cast<const float4*>(b);

    // yi = W[row]+b: lane holds float4 indices {gl, gl+8, gl+16, gl+24}
    // (16 elems), replicated across the 4 groups. ci = b.yi, rn = ||yi||^2.
    float4 yi[4];
    float ci = 0.f, rn = 0.f;
    #pragma unroll
    for (int i = 0; i < 4; i++) {
        float4 wv = W4[row * 32 + i * 8 + gl];
        float4 bv = B4[i * 8 + gl];
        yi[i].x = wv.x + bv.x; yi[i].y = wv.y + bv.y;
        yi[i].z = wv.z + bv.z; yi[i].w = wv.w + bv.w;
        ci += bv.x*yi[i].x + bv.y*yi[i].y + bv.z*yi[i].z + bv.w*yi[i].w;
        rn += yi[i].x*yi[i].x + yi[i].y*yi[i].y
            + yi[i].z*yi[i].z + yi[i].w*yi[i].w;
    }
    #pragma unroll
    for (int off = 1; off < 8; off <<= 1) {
        ci += __shfl_xor_sync(FULLM, ci, off);
        rn += __shfl_xor_sync(FULLM, rn, off);
    }

    float acc = (w == 0 && lane == 0) ? 0.5f * LMBD * rn : 0.f;

    const int base4 = w * 256;
    int cnt = 0;   // warp-uniform
    float4 av[4];

    // group dot: same j on all lanes -> full dot valid on every lane
    auto gdot = [&](int j) -> float {
        const float4* yr = W4 + j * 32 + gl;
        float4 z0 = yr[0], z1 = yr[8], z2 = yr[16], z3 = yr[24];
        float p = z0.x*yi[0].x + z0.y*yi[0].y + z0.z*yi[0].z + z0.w*yi[0].w;
        p += z1.x*yi[1].x + z1.y*yi[1].y + z1.z*yi[1].z + z1.w*yi[1].w;
        p += z2.x*yi[2].x + z2.y*yi[2].y + z2.z*yi[2].z + z2.w*yi[2].w;
        p += z3.x*yi[3].x + z3.y*yi[3].y + z3.z*yi[3].z + z3.w*yi[3].w;
        p += __shfl_xor_sync(FULLM, p, 1);
        p += __shfl_xor_sync(FULLM, p, 2);
        p += __shfl_xor_sync(FULLM, p, 4);
        return p;
    };

    // compact the current av[4] chunk; extras/overflow deferred to one ballot
    auto compact_chunk = [&](int coff) {
        unsigned exm = 0u;   // 4 bits per k: extra-component masks
        unsigned ovm = 0u;   // 1 bit per k: overflow
        #pragma unroll
        for (int k = 0; k < 4; k++) {
            float4 a4 = av[k];
            unsigned nzm = (a4.x > 0.f ? 1u : 0u) | (a4.y > 0.f ? 2u : 0u)
                         | (a4.z > 0.f ? 4u : 0u) | (a4.w > 0.f ? 8u : 0u);
            bool nz = nzm != 0u;
            unsigned m = __ballot_sync(FULLM, nz);
            if (m) {
                int e0 = __ffs(nzm) - 1;
                float a0 = (e0 <= 0) ? a4.x : (e0 == 1) ? a4.y
                         : (e0 == 2) ? a4.z : a4.w;
                int pos = cnt + __popc(m & ltm);
                bool ovf = nz && pos >= QEFF;
                if (nz && !ovf) {
                    qa[w][pos] = a0;
                    qj[w][pos] = (base4 + coff + k * 32 + lane) * 4 + e0;
                }
                exm |= (nz ? (nzm & (nzm - 1u)) : 0u) << (k * 4);
                if (ovf) ovm |= 1u << k;
                cnt = min(cnt + __popc(m), QEFF);
            }
        }
        unsigned mo = __ballot_sync(FULLM, (exm | ovm) != 0u);
        while (mo) {   // rare path
            int src = __ffs(mo) - 1; mo &= mo - 1;
            unsigned sex = __shfl_sync(FULLM, exm, src);
            unsigned sov = __shfl_sync(FULLM, ovm, src);
            #pragma unroll
            for (int k = 0; k < 4; k++) {
                unsigned tk = (sex >> (k * 4)) & 0xFu;
                if (sov & (1u << k)) tk = 0xFu;   // overflow: redo whole float4
                if (tk) {
                    float bx = __shfl_sync(FULLM, av[k].x, src);
                    float by = __shfl_sync(FULLM, av[k].y, src);
                    float bz = __shfl_sync(FULLM, av[k].z, src);
                    float bw = __shfl_sync(FULLM, av[k].w, src);
                    int jb = (base4 + coff + k * 32 + src) * 4;
                    while (tk) {
                        int e = __ffs(tk) - 1; tk &= tk - 1;
                        float a = (e == 0) ? bx : (e == 1) ? by
                                : (e == 2) ? bz : bw;
                        if (a > 0.f) {
                            float p = gdot(jb + e);
                            if (lane == 0) {
                                float rr = a - (p + ci);
                                acc = fmaf(0.5f * rr, rr, acc);
                            }
                        }
                    }
                }
            }
        }
    };

    // drain: 4 entries/iter (one per group); 16 W-loads batched, 3-shfl reduce
    auto drain = [&]() {
        int cntp = (cnt + 3) & ~3;
        if (lane < cntp - cnt) { qa[w][cnt + lane] = 0.f; qj[w][cnt + lane] = 0; }
        __syncwarp();
        for (int base = 0; base < cntp; base += 4) {
            float a = qa[w][base + grp];   // group-broadcast smem reads
            int   j = qj[w][base + grp];
            const float4* yr = W4 + j * 32 + gl;
            float4 z0 = yr[0], z1 = yr[8], z2 = yr[16], z3 = yr[24];
            float p = z0.x*yi[0].x + z0.y*yi[0].y + z0.z*yi[0].z + z0.w*yi[0].w;
            p += z1.x*yi[1].x + z1.y*yi[1].y + z1.z*yi[1].z + z1.w*yi[1].w;
            p += z2.x*yi[2].x + z2.y*yi[2].y + z2.z*yi[2].z + z2.w*yi[2].w;
            p += z3.x*yi[3].x + z3.y*yi[3].y + z3.z*yi[3].z + z3.w*yi[3].w;
            p += __shfl_xor_sync(FULLM, p, 1);
            p += __shfl_xor_sync(FULLM, p, 2);
            p += __shfl_xor_sync(FULLM, p, 4);
            if (a > 0.f && gl == 0) {
                float rr = a - (p + ci);
                acc = fmaf(0.5f * rr, rr, acc);
            }
        }
        __syncwarp();
        cnt = 0;
    };

    // chunk 0 loads (streaming; A read exactly once)
    #pragma unroll
    for (int k = 0; k < 4; k++) av[k] = __ldcs(A4 + base4 + k * 32 + lane);
    compact_chunk(0);
    // stash chunk-0 queue count, then get chunk-1 loads in flight
    #pragma unroll
    for (int k = 0; k < 4; k++) {
        float4 t = __ldcs(A4 + base4 + 128 + k * 32 + lane);
        // delay overwrite of av until compact_chunk(0) extras are done (they are)
        av[k] = t;
    }
    drain();
    compact_chunk(128);
    drain();

    // block reduce (acc lives on gl==0 lanes)
    #pragma unroll
    for (int off = 16; off > 0; off >>= 1)
        acc += __shfl_xor_sync(FULLM, acc, off);
    if (lane == 0) sp[w] = acc;
    __syncthreads();

    if (threadIdx.x == 0) {
        float part = 0.f;
        #pragma unroll
        for (int i = 0; i < 8; i++) part += sp[i];
        atomicAdd(&g_sum, part);
        __threadfence();
        unsigned c = atomicAdd(&g_count, 1u);
        if (c == gridDim.x - 1) {
            float total = atomicExch(&g_sum, 0.f);
            atomicExch(&g_count, 0u);
            out[0] = total;
        }
    }
}

extern "C" void kernel_launch(void* const* d_in, const int* in_sizes, int n_in,
                              void* d_out, int out_size) {
    const float* A = (const float*)d_in[0];
    const float* W = (const float*)d_in[1];
    const float* b = (const float*)d_in[2];
    float* out = (float*)d_out;

    main_kernel<<<GN, 256>>>(A, W, b, out);
}